// round 12
// baseline (speedup 1.0000x reference)
#include <cuda_runtime.h>
#include <math.h>

// Hyperbolic conv constants (must match reference)
#define CC    0.05f
#define SQC   0.22360679774997896f          // sqrt(0.05)
#define MINN  1e-15f
#define MAXN  (0.996f / SQC)                // (1 - 4e-3)/sqrt(c)
#define MAXN2 (MAXN * MAXN)

typedef unsigned long long u64;

// u tile stride padded to 68 floats (272B = 17*16B) so every row is 16B aligned
#define TW    68
#define TSZ   (66 * TW)                     // 4488 floats per tile
#define TSZ4  (TSZ / 4)                     // 1122 float4

// Scratch: u = logmap0(pad(x)), [b][j][66*68], 32*64*4488 floats (~36.8MB)
__device__ float g_u[9191424];
__device__ float g_bh[128];                 // expmap0(bias)

// ---------------------------------------------------------------------------
// packed f32x2 + fast-approx + cp.async helpers
// ---------------------------------------------------------------------------
__device__ __forceinline__ u64 pk(float a, float b) {
    u64 r;
    asm("mov.b64 %0, {%1, %2};" : "=l"(r)
        : "r"(__float_as_uint(a)), "r"(__float_as_uint(b)));
    return r;
}
__device__ __forceinline__ float2 unpk(u64 v) {
    unsigned lo, hi;
    asm("mov.b64 {%0, %1}, %2;" : "=r"(lo), "=r"(hi) : "l"(v));
    return make_float2(__uint_as_float(lo), __uint_as_float(hi));
}
__device__ __forceinline__ u64 fma2(u64 a, u64 b, u64 c) {
    u64 d;
    asm("fma.rn.f32x2 %0, %1, %2, %3;" : "=l"(d) : "l"(a), "l"(b), "l"(c));
    return d;
}
__device__ __forceinline__ float fexp2(float x){ float r; asm("ex2.approx.f32 %0, %1;" : "=f"(r) : "f"(x)); return r; }
__device__ __forceinline__ float frcp (float x){ float r; asm("rcp.approx.f32 %0, %1;" : "=f"(r) : "f"(x)); return r; }
__device__ __forceinline__ float frsq (float x){ float r; asm("rsqrt.approx.f32 %0, %1;" : "=f"(r) : "f"(x)); return r; }

__device__ __forceinline__ void cpasync16(unsigned saddr, const void* g) {
    asm volatile("cp.async.cg.shared.global [%0], [%1], 16;" :: "r"(saddr), "l"(g));
}
#define CP_COMMIT() asm volatile("cp.async.commit_group;")
#define CP_WAIT0()  asm volatile("cp.async.wait_group 0;")

__device__ __forceinline__ float artanhc(float z) {
    z = fminf(z, 1.0f - 1e-7f);             // z >= 0 always here
    return 0.5f * (log1pf(z) - log1pf(-z));
}

// ---------------------------------------------------------------------------
// Kernel 1: u = logmap0(pad(x)) per (b, cin) row (precise), stride-68 layout.
// Block 2048 additionally computes b_h = expmap0(bias).
// ---------------------------------------------------------------------------
__global__ __launch_bounds__(256) void u_kernel(const float* __restrict__ x,
                                                const float* __restrict__ bias) {
    int row = blockIdx.x;
    int t = threadIdx.x;

    if (row == 2048) {                      // bias block
        if (t < 128) {
            float v = bias[t];
            float p = v * v;
            #pragma unroll
            for (int o = 16; o > 0; o >>= 1) p += __shfl_xor_sync(0xffffffffu, p, o);
            __shared__ float smb[4];
            if ((t & 31) == 0) smb[t >> 5] = p;
            __syncwarp();
            asm volatile("bar.sync 1, 128;");
            float s2 = smb[0] + smb[1] + smb[2] + smb[3];
            float bn = fmaxf(sqrtf(s2), MINN);
            float z  = SQC * bn;
            g_bh[t] = tanhf(z) / z * v;
        }
        return;
    }

    const float* xr = x + (size_t)row * 4096;

    float p = 0.0f;
    #pragma unroll
    for (int k = 0; k < 16; k++) { float v = xr[t + (k << 8)]; p += v * v; }
    #pragma unroll
    for (int o = 16; o > 0; o >>= 1) p += __shfl_xor_sync(0xffffffffu, p, o);
    __shared__ float sm[8];
    __shared__ float s_scale;
    if ((t & 31) == 0) sm[t >> 5] = p;
    __syncthreads();
    if (t == 0) {
        float s2 = 0.0f;
        #pragma unroll
        for (int i = 0; i < 8; i++) s2 += sm[i];
        float yn = fmaxf(sqrtf(s2), MINN);
        float z  = SQC * yn;
        s_scale  = artanhc(z) / z;
    }
    __syncthreads();
    float sc = s_scale;

    float* ur = g_u + (size_t)row * TSZ;
    for (int idx = t; idx < TSZ; idx += 256) {
        int r = idx / TW, c = idx - r * TW;
        float v = 0.0f;
        if (r >= 1 && r <= 64 && c >= 1 && c <= 64)
            v = xr[(r - 1) * 64 + (c - 1)] * sc;
        ur[idx] = v;
    }
}

// ---------------------------------------------------------------------------
// Mobius scan scalar math — short chain (no sqrt on common path).
// acc = P*q;  qv = <q,v>.  Returns (sA, sBt); updates a2 = |acc'|^2.
// ---------------------------------------------------------------------------
__device__ __forceinline__ float2 step_scalars(float sv2, float qv, float P, float& a2) {
    float z2 = CC * sv2;                           // z^2
    float tau;
    if (z2 < 0.0625f) {                            // z < 0.25 (always, this data)
        tau = 1.0f + z2 * (-0.33333334f + z2 * (0.13333334f - z2 * 0.053968254f));
    } else {
        float vn = sv2 * frsq(fmaxf(sv2, 1e-28f));
        float z  = SQC * vn;
        float t  = fexp2(z * 2.8853901f);          // e^{2z}
        tau = (t - 1.0f) * frcp((t + 1.0f) * z);
    }
    float tn2 = tau * tau * sv2;                   // |t|^2 before project
    float ts  = tau;
    if (tn2 > MAXN2) ts = tau * (MAXN * frsq(tn2));  // project(t), rare
    float y2  = ts * ts * sv2;
    float xy  = ts * (P * qv);
    float x2  = a2;
    float A   = 1.0f + 2.0f * CC * xy + CC * y2;
    float B   = 1.0f - CC * x2;
    float den = fmaxf(1.0f + 2.0f * CC * xy + CC * CC * x2 * y2, MINN);
    float inv = frcp(den);
    float n2  = (A * A * x2 + 2.0f * A * B * xy + B * B * y2) * (inv * inv);
    float ps  = 1.0f;
    if (n2 > MAXN2) ps = MAXN * frsq(fmaxf(n2, 1e-28f));  // project(acc'), rare
    a2 = ps * ps * n2;
    return make_float2(A * inv * ps, B * inv * ps * ts);
}

__device__ __forceinline__ float2 final_scalars(float sacc, float a2, float bh) {
    float y2  = 4096.0f * bh * bh;
    float xy  = bh * sacc;
    float x2  = a2;
    float A   = 1.0f + 2.0f * CC * xy + CC * y2;
    float B   = 1.0f - CC * x2;
    float den = fmaxf(1.0f + 2.0f * CC * xy + CC * CC * x2 * y2, MINN);
    float inv = frcp(den);
    float n2  = (A * A * x2 + 2.0f * A * B * xy + B * B * y2) * (inv * inv);
    float ps  = 1.0f;
    if (n2 > MAXN2) ps = MAXN * frsq(fmaxf(n2, 1e-28f));
    return make_float2(A * inv * ps, B * inv * ps * bh);
}

// load one 6-wide window row (16B-aligned) as 5 overlapping f32x2 pairs
__device__ __forceinline__ void loadrow(const float* p, u64* row) {
    float4 a = *(const float4*)p;           // floats 0-3 (LDS.128)
    float2 b = *(const float2*)(p + 4);     // floats 4-5 (LDS.64)
    row[0] = pk(a.x, a.y);
    row[1] = pk(a.y, a.z);
    row[2] = pk(a.z, a.w);
    row[3] = pk(a.w, b.x);
    row[4] = pk(b.x, b.y);
}

// ---------------------------------------------------------------------------
// Kernel 2: ONE CHANNEL per CTA (grid 128 x 32), 256 threads, 4x4 outputs
// each, columns packed f32x2. Halved register state -> 3 CTAs/SM (occupancy
// play). cp.async double buffer, one barrier per scan step, lane-split
// butterfly (5 SHFL/iter), scalar chain redundant per thread.
// ---------------------------------------------------------------------------
__global__ __launch_bounds__(256, 3)
void main_kernel(const float* __restrict__ w, float* __restrict__ out) {
    const int b    = blockIdx.y;
    const int c    = blockIdx.x;        // output channel
    const int tid  = threadIdx.x;
    const int ty   = tid >> 4;
    const int tx   = tid & 15;
    const int lane = tid & 31;
    const int wid  = tid >> 5;
    const int par  = lane & 1;          // 0: reduce |v|^2, 1: reduce <q,v>

    __shared__ float  su[2 * TSZ];      // double-buffered 66x68 tile
    __shared__ u64    swp[576];         // weights pre-duplicated (w,w)
    __shared__ float2 sred[2][8];       // [buf][warp] -> (sv2, qv) partials

    for (int i = tid; i < 576; i += 256)
        swp[i] = pk(w[(size_t)c * 576 + i], w[(size_t)c * 576 + i]);

    const unsigned su_s = (unsigned)__cvta_generic_to_shared(su);
    const float4* gbase = (const float4*)(g_u + (size_t)(b * 64) * TSZ);
    const int tail = tid + 1024;            // only first 98 threads copy chunk 5

    // preload tile 0 into buf0 via cp.async
    #pragma unroll
    for (int k = 0; k < 4; k++) {
        int i = tid + (k << 8);
        cpasync16(su_s + i * 16, gbase + i);
    }
    if (tail < TSZ4) cpasync16(su_s + tail * 16, gbase + tail);
    CP_COMMIT();
    CP_WAIT0();
    __syncthreads();

    u64 qa[8];                          // acc = P * q, packed col pairs
    #pragma unroll
    for (int i = 0; i < 8; i++) qa[i] = 0ull;
    float a2m = 0.0f, Pm = 1.0f;        // scan state (redundant per thread)

    const int baseoff = (4 * ty) * TW + 4 * tx;

    #pragma unroll 2
    for (int j = 0; j < 64; j++) {
        const int cur = j & 1;

        // ---- branchless async prefetch of tile (j+1)&63 into other buffer ----
        {
            const float4* gn = gbase + (size_t)((j + 1) & 63) * TSZ4;
            unsigned sn = su_s + (cur ^ 1) * (TSZ * 4);
            #pragma unroll
            for (int k = 0; k < 4; k++) {
                int i = tid + (k << 8);
                cpasync16(sn + i * 16, gn + i);
            }
            if (tail < TSZ4) cpasync16(sn + tail * 16, gn + tail);
            CP_COMMIT();
        }

        const float* basep = su + cur * TSZ + baseoff;
        const u64* wp = &swp[j * 9];

        // ---- conv: rolling 3-row window; weights broadcast from smem ----
        u64 v[8];
        u64 rwin[3][5];
        #pragma unroll
        for (int r = 0; r < 3; r++) loadrow(basep + r * TW, rwin[r]);

        #pragma unroll
        for (int orow = 0; orow < 4; orow++) {
            u64 s0 = 0ull, s1 = 0ull;
            #pragma unroll
            for (int r = 0; r < 3; r++) {
                const u64* rw = rwin[(orow + r) % 3];
                #pragma unroll
                for (int k = 0; k < 3; k++) {
                    u64 wa = wp[r * 3 + k];
                    s0 = fma2(rw[k],     wa, s0);
                    s1 = fma2(rw[2 + k], wa, s1);
                }
            }
            v[orow * 2]     = s0;
            v[orow * 2 + 1] = s1;
            if (orow < 3) loadrow(basep + (orow + 3) * TW, rwin[orow % 3]);
        }

        // ---- fused packed reduction: |v|^2 and <q,v> ----
        u64 sq = 0ull, av = 0ull;
        #pragma unroll
        for (int i = 0; i < 8; i++) {
            sq = fma2(v[i], v[i], sq);
            av = fma2(qa[i], v[i], av);
        }
        float2 pa = unpk(sq), pb = unpk(av);
        float s_p = pa.x + pa.y;              // |v|^2 partial
        float d_p = pb.x + pb.y;              // <q,v> partial

        // ---- lane-split butterfly: even lanes own s, odd own d (5 SHFL) ----
        float m  = par ? d_p : s_p;
        float ot = par ? s_p : d_p;
        m += __shfl_xor_sync(0xffffffffu, ot, 1);
        #pragma unroll
        for (int o = 2; o <= 16; o <<= 1)
            m += __shfl_xor_sync(0xffffffffu, m, o);
        if (lane < 2) ((float*)&sred[cur][wid])[par] = m;

        // prefetch must land before the barrier publishes the buffer
        CP_WAIT0();
        __syncthreads();                      // single barrier per scan step

        // tree-sum the 8 warp partials (float2 broadcast reads)
        float2 r0 = sred[cur][0], r1 = sred[cur][1];
        float2 r2 = sred[cur][2], r3 = sred[cur][3];
        float2 r4 = sred[cur][4], r5 = sred[cur][5];
        float2 r6 = sred[cur][6], r7 = sred[cur][7];
        float sv2 = ((r0.x + r1.x) + (r2.x + r3.x)) + ((r4.x + r5.x) + (r6.x + r7.x));
        float qv  = ((r0.y + r1.y) + (r2.y + r3.y)) + ((r4.y + r5.y) + (r6.y + r7.y));

        // ---- scalar chain (redundant per thread, deterministic) ----
        float2 s = step_scalars(sv2, qv, Pm, a2m);
        Pm *= s.x;
        float qc = s.y * frcp(Pm);
        u64 QC = pk(qc, qc);
        #pragma unroll
        for (int i = 0; i < 8; i++)
            qa[i] = fma2(QC, v[i], qa[i]);
    }

    // ---- epilogue: mobius bias add + project (acc = P*q) ----
    float sa = 0.0f;
    #pragma unroll
    for (int i = 0; i < 8; i++) {
        float2 p0 = unpk(qa[i]); sa += p0.x + p0.y;
    }
    #pragma unroll
    for (int o = 16; o > 0; o >>= 1)
        sa += __shfl_xor_sync(0xffffffffu, sa, o);
    if (lane == 0) sred[0][wid] = make_float2(sa, 0.f);
    __syncthreads();
    float tm = ((sred[0][0].x + sred[0][1].x) + (sred[0][2].x + sred[0][3].x))
             + ((sred[0][4].x + sred[0][5].x) + (sred[0][6].x + sred[0][7].x));

    float2 f = final_scalars(Pm * tm, a2m, g_bh[c]);
    float fx = f.x * Pm;
    u64 FA = pk(fx, fx), FB = pk(f.y, f.y);

    u64* o0 = (u64*)(out + ((size_t)(b * 128 + c)) * 4096);
    #pragma unroll
    for (int orow = 0; orow < 4; orow++) {
        #pragma unroll
        for (int p = 0; p < 2; p++) {
            int pos = (4 * ty + orow) * 32 + 2 * tx + p;   // in float2 units
            o0[pos] = fma2(FA, qa[orow * 2 + p], FB);
        }
    }
}

// ---------------------------------------------------------------------------
extern "C" void kernel_launch(void* const* d_in, const int* in_sizes, int n_in,
                              void* d_out, int out_size) {
    const float* x    = (const float*)d_in[0];   // [32,64,64,64]
    const float* wgt  = (const float*)d_in[1];   // [128,64,3,3]
    const float* bias = (const float*)d_in[2];   // [128]
    float* out = (float*)d_out;                  // [32,128,64,64]

    u_kernel<<<2049, 256>>>(x, bias);            // block 2048 also does bias
    dim3 grid(128, 32);                          // (cout, bs)
    main_kernel<<<grid, 256>>>(wgt, out);
}